// round 1
// baseline (speedup 1.0000x reference)
#include <cuda_runtime.h>
#include <cuda_bf16.h>
#include <cstdint>

#define Nn 8192
#define Dd 512
#define EPSf 1e-8f
#define NCHUNK 8
#define COLS_PER_CHUNK (Nn / NCHUNK)   // 1024

#define BM 128
#define BN 128
#define BK 32
#define AST 40   // padded shared stride (bf16 elems): 32 + 8, 80B rows (16B aligned)

// ---- scratch (static device allocations; no cudaMalloc anywhere) ----
__device__ __nv_bfloat16 g_Ahat[(size_t)Nn * Dd];
__device__ __nv_bfloat16 g_Phat[(size_t)Nn * Dd];
__device__ float g_pos[Nn];
__device__ float g_diag[Nn];
__device__ float g_norm2[Nn];
__device__ float g_partial[NCHUNK][Nn];

// ============================================================
// Kernel 1: per-row norms, normalized bf16 copies, pos/diag/l2
// One warp per row. grid = Nn/8 blocks x 256 threads.
// ============================================================
__global__ void __launch_bounds__(256) k_norm(const float* __restrict__ ex) {
    int gw = (blockIdx.x * 256 + threadIdx.x) >> 5;   // row id
    int lane = threadIdx.x & 31;
    if (gw >= Nn) return;

    const float4* a4 = reinterpret_cast<const float4*>(ex + (size_t)gw * 2 * Dd);
    const float4* p4 = a4 + Dd / 4;

    float4 av[4], pv[4];
    float an2 = 0.f, pn2 = 0.f, dt = 0.f;
#pragma unroll
    for (int i = 0; i < 4; i++) {
        av[i] = a4[lane + 32 * i];
        pv[i] = p4[lane + 32 * i];
        an2 += av[i].x * av[i].x + av[i].y * av[i].y + av[i].z * av[i].z + av[i].w * av[i].w;
        pn2 += pv[i].x * pv[i].x + pv[i].y * pv[i].y + pv[i].z * pv[i].z + pv[i].w * pv[i].w;
        dt  += av[i].x * pv[i].x + av[i].y * pv[i].y + av[i].z * pv[i].z + av[i].w * pv[i].w;
    }
#pragma unroll
    for (int o = 16; o; o >>= 1) {
        an2 += __shfl_xor_sync(0xffffffffu, an2, o);
        pn2 += __shfl_xor_sync(0xffffffffu, pn2, o);
        dt  += __shfl_xor_sync(0xffffffffu, dt, o);
    }
    float an = sqrtf(an2), pn = sqrtf(pn2);
    float ia = 1.0f / an, ip = 1.0f / pn;

#pragma unroll
    for (int i = 0; i < 4; i++) {
        int idx = (lane + 32 * i) * 4;
        __nv_bfloat162 h0 = __floats2bfloat162_rn(av[i].x * ia, av[i].y * ia);
        __nv_bfloat162 h1 = __floats2bfloat162_rn(av[i].z * ia, av[i].w * ia);
        uint2 u;
        u.x = *reinterpret_cast<uint32_t*>(&h0);
        u.y = *reinterpret_cast<uint32_t*>(&h1);
        *reinterpret_cast<uint2*>(&g_Ahat[(size_t)gw * Dd + idx]) = u;

        __nv_bfloat162 q0 = __floats2bfloat162_rn(pv[i].x * ip, pv[i].y * ip);
        __nv_bfloat162 q1 = __floats2bfloat162_rn(pv[i].z * ip, pv[i].w * ip);
        uint2 w;
        w.x = *reinterpret_cast<uint32_t*>(&q0);
        w.y = *reinterpret_cast<uint32_t*>(&q1);
        *reinterpret_cast<uint2*>(&g_Phat[(size_t)gw * Dd + idx]) = w;
    }
    if (lane == 0) {
        g_pos[gw]   = dt / fmaxf(an * pn, EPSf);
        g_diag[gw]  = an2 / fmaxf(an2, EPSf);
        g_norm2[gw] = an2 + pn2;
    }
}

// ============================================================
// Kernel 2: bf16 mma.sync GEMM (A_hat @ P_hat^T) with fused
// exp-row-sum epilogue. Deterministic chunked partials.
// grid = (NCHUNK, Nn/BM), block = 256 (8 warps: 4M x 2N).
// ============================================================
__device__ __forceinline__ void cpa16(uint32_t dst, const void* src) {
    asm volatile("cp.async.cg.shared.global [%0], [%1], 16;\n" :: "r"(dst), "l"(src));
}

__device__ __forceinline__ void mma16816(float* c, const uint32_t* a, uint32_t b0, uint32_t b1) {
    asm volatile(
        "mma.sync.aligned.m16n8k16.row.col.f32.bf16.bf16.f32 "
        "{%0,%1,%2,%3}, {%4,%5,%6,%7}, {%8,%9}, {%0,%1,%2,%3};\n"
        : "+f"(c[0]), "+f"(c[1]), "+f"(c[2]), "+f"(c[3])
        : "r"(a[0]), "r"(a[1]), "r"(a[2]), "r"(a[3]), "r"(b0), "r"(b1));
}

__global__ void __launch_bounds__(256, 1) k_gemm() {
    __shared__ __nv_bfloat16 sA[2][BM * AST];
    __shared__ __nv_bfloat16 sB[2][BN * AST];
    __shared__ float srow[2][BM];

    const int tid = threadIdx.x;
    const int lane = tid & 31;
    const int warp = tid >> 5;
    const int wm = warp >> 1;   // 0..3
    const int wn = warp & 1;    // 0..1
    const int rb = blockIdx.y;
    const int chunk = blockIdx.x;
    const int row0 = rb * BM;

    const __nv_bfloat16* __restrict__ Ag = g_Ahat + (size_t)row0 * Dd;

    const uint32_t sAb = (uint32_t)__cvta_generic_to_shared(&sA[0][0]);
    const uint32_t sBb = (uint32_t)__cvta_generic_to_shared(&sB[0][0]);
    const uint32_t stageA = BM * AST * 2;  // bytes
    const uint32_t stageB = BN * AST * 2;

    float rowacc[4] = {0.f, 0.f, 0.f, 0.f};

    for (int jt = 0; jt < COLS_PER_CHUNK / BN; ++jt) {
        const int jcol = chunk * COLS_PER_CHUNK + jt * BN;
        const __nv_bfloat16* __restrict__ Bg = g_Phat + (size_t)jcol * Dd;

        float c[2][8][4];
#pragma unroll
        for (int mi = 0; mi < 2; mi++)
#pragma unroll
            for (int nj = 0; nj < 8; nj++)
#pragma unroll
                for (int k = 0; k < 4; k++) c[mi][nj][k] = 0.f;

        // prologue: stage 0 loads
        {
#pragma unroll
            for (int u = 0; u < 2; u++) {
                int e = tid + u * 256;
                int r = e >> 2, seg = e & 3;
                cpa16(sAb + (uint32_t)((r * AST + seg * 8) * 2), Ag + r * Dd + seg * 8);
                cpa16(sBb + (uint32_t)((r * AST + seg * 8) * 2), Bg + r * Dd + seg * 8);
            }
            asm volatile("cp.async.commit_group;\n" ::);
        }

        int s = 0;
#pragma unroll 1
        for (int kt = 0; kt < Dd / BK; ++kt) {
            asm volatile("cp.async.wait_group 0;\n" ::);
            __syncthreads();

            if (kt + 1 < Dd / BK) {
                const int k0 = (kt + 1) * BK;
                const uint32_t so = (uint32_t)(s ^ 1);
#pragma unroll
                for (int u = 0; u < 2; u++) {
                    int e = tid + u * 256;
                    int r = e >> 2, seg = e & 3;
                    cpa16(sAb + so * stageA + (uint32_t)((r * AST + seg * 8) * 2),
                          Ag + r * Dd + k0 + seg * 8);
                    cpa16(sBb + so * stageB + (uint32_t)((r * AST + seg * 8) * 2),
                          Bg + r * Dd + k0 + seg * 8);
                }
            }
            asm volatile("cp.async.commit_group;\n" ::);

            // compute stage s: two k16 steps
#pragma unroll
            for (int ks = 0; ks < 2; ++ks) {
                uint32_t a[2][4];
#pragma unroll
                for (int mi = 0; mi < 2; mi++) {
                    uint32_t addr = sAb + (uint32_t)s * stageA +
                        (uint32_t)((((wm * 32 + mi * 16 + (lane & 15)) * AST) +
                                    ks * 16 + ((lane >> 4) << 3)) << 1);
                    asm volatile(
                        "ldmatrix.sync.aligned.m8n8.x4.shared.b16 {%0,%1,%2,%3}, [%4];\n"
                        : "=r"(a[mi][0]), "=r"(a[mi][1]), "=r"(a[mi][2]), "=r"(a[mi][3])
                        : "r"(addr));
                }
#pragma unroll
                for (int np = 0; np < 4; np++) {
                    uint32_t b[4];
                    int brow = wn * 64 + np * 16 + (lane & 7) + ((lane >> 4) << 3);
                    int bk = ks * 16 + ((lane >> 3) & 1) * 8;
                    uint32_t addr = sBb + (uint32_t)s * stageB +
                        (uint32_t)((brow * AST + bk) << 1);
                    asm volatile(
                        "ldmatrix.sync.aligned.m8n8.x4.shared.b16 {%0,%1,%2,%3}, [%4];\n"
                        : "=r"(b[0]), "=r"(b[1]), "=r"(b[2]), "=r"(b[3])
                        : "r"(addr));
#pragma unroll
                    for (int mi = 0; mi < 2; mi++) {
                        mma16816(c[mi][np * 2 + 0], a[mi], b[0], b[1]);
                        mma16816(c[mi][np * 2 + 1], a[mi], b[2], b[3]);
                    }
                }
            }
            __syncthreads();
            s ^= 1;
        }

        // epilogue: exp + row-sum (diag fix when this tile sits on the diagonal)
        const bool hd = (row0 == jcol);
#pragma unroll
        for (int mi = 0; mi < 2; mi++) {
            float s0 = 0.f, s1 = 0.f;
            int gi0 = row0 + wm * 32 + mi * 16 + (lane >> 2);
            int gi8 = gi0 + 8;
#pragma unroll
            for (int nj = 0; nj < 8; nj++) {
                int gj = jcol + wn * 64 + nj * 8 + ((lane & 3) << 1);
                float v0 = c[mi][nj][0], v1 = c[mi][nj][1];
                float v2 = c[mi][nj][2], v3 = c[mi][nj][3];
                if (hd) {
                    if (gi0 == gj)     v0 = g_diag[gi0];
                    if (gi0 == gj + 1) v1 = g_diag[gi0];
                    if (gi8 == gj)     v2 = g_diag[gi8];
                    if (gi8 == gj + 1) v3 = g_diag[gi8];
                }
                s0 += __expf(v0) + __expf(v1);
                s1 += __expf(v2) + __expf(v3);
            }
            rowacc[mi * 2 + 0] += s0;
            rowacc[mi * 2 + 1] += s1;
        }
    }

    // cross-lane reduce (lanes sharing a row differ only in lane&3)
#pragma unroll
    for (int k = 0; k < 4; k++) {
        rowacc[k] += __shfl_xor_sync(0xffffffffu, rowacc[k], 1);
        rowacc[k] += __shfl_xor_sync(0xffffffffu, rowacc[k], 2);
    }
    if ((lane & 3) == 0) {
        int lr = wm * 32 + (lane >> 2);
        srow[wn][lr +  0] = rowacc[0];
        srow[wn][lr +  8] = rowacc[1];
        srow[wn][lr + 16] = rowacc[2];
        srow[wn][lr + 24] = rowacc[3];
    }
    __syncthreads();
    if (tid < BM) g_partial[chunk][row0 + tid] = srow[0][tid] + srow[1][tid];
}

// ============================================================
// Kernel 3: final deterministic reduction -> scalar loss
// ============================================================
__global__ void __launch_bounds__(1024) k_final(float* __restrict__ out) {
    __shared__ float sL[1024];
    __shared__ float sS[1024];
    int tid = threadIdx.x;
    float loss = 0.f, sq = 0.f;
    for (int i = tid; i < Nn; i += 1024) {
        float rs = 0.f;
#pragma unroll
        for (int cidx = 0; cidx < NCHUNK; cidx++) rs += g_partial[cidx][i];
        float pos = g_pos[i];
        loss += logf(rs + __expf(pos)) - pos;
        sq += g_norm2[i];
    }
    sL[tid] = loss;
    sS[tid] = sq;
    __syncthreads();
    for (int o = 512; o; o >>= 1) {
        if (tid < o) { sL[tid] += sL[tid + o]; sS[tid] += sS[tid + o]; }
        __syncthreads();
    }
    if (tid == 0) out[0] = sL[0] / (float)Nn + 0.02f * sqrtf(sS[0]);
}

// ============================================================
extern "C" void kernel_launch(void* const* d_in, const int* in_sizes, int n_in,
                              void* d_out, int out_size) {
    const float* ex = (const float*)d_in[0];
    (void)in_sizes; (void)n_in; (void)out_size;

    k_norm<<<Nn / 8, 256>>>(ex);

    dim3 g(NCHUNK, Nn / BM);
    k_gemm<<<g, 256>>>();

    k_final<<<1, 1024>>>((float*)d_out);
}

// round 3
// speedup vs baseline: 1.5341x; 1.5341x over previous
#include <cuda_runtime.h>
#include <cuda_bf16.h>
#include <cstdint>

#define Nn 8192
#define Dd 512
#define EPSf 1e-8f

#define NCHUNK 16        // col chunks (grid.x)
#define JT 4             // 128-col tiles per chunk
#define KT 8             // K steps of 64 bytes
#define NST 4            // B pipeline stages
#define BM 128
#define BN 128

#define A_BYTES (BM * Dd)       // 65536 — A tile resident
#define B_STG (BN * 64)         // 8192 per stage
#define DYN_SMEM (A_BYTES + NST * B_STG)   // 98304

// ---- scratch ----
__device__ unsigned char g_A8[(size_t)Nn * Dd];
__device__ unsigned char g_P8[(size_t)Nn * Dd];
__device__ float g_pos[Nn];
__device__ float g_diag[Nn];
__device__ float g_norm2[Nn];
__device__ float g_partial[NCHUNK][Nn];

__device__ __forceinline__ void cpa16(uint32_t dst, const void* src) {
    asm volatile("cp.async.cg.shared.global [%0], [%1], 16;\n" :: "r"(dst), "l"(src));
}
__device__ __forceinline__ void cp_commit() {
    asm volatile("cp.async.commit_group;\n" ::);
}
#define CP_WAIT(n) asm volatile("cp.async.wait_group %0;\n" :: "n"(n))

__device__ __forceinline__ void ldm4(uint32_t* r, uint32_t addr) {
    asm volatile("ldmatrix.sync.aligned.m8n8.x4.shared.b16 {%0,%1,%2,%3}, [%4];\n"
                 : "=r"(r[0]), "=r"(r[1]), "=r"(r[2]), "=r"(r[3]) : "r"(addr));
}
__device__ __forceinline__ void mma_fp8(float* c, const uint32_t* a, uint32_t b0, uint32_t b1) {
    asm volatile(
        "mma.sync.aligned.m16n8k32.row.col.f32.e4m3.e4m3.f32 "
        "{%0,%1,%2,%3}, {%4,%5,%6,%7}, {%8,%9}, {%0,%1,%2,%3};\n"
        : "+f"(c[0]), "+f"(c[1]), "+f"(c[2]), "+f"(c[3])
        : "r"(a[0]), "r"(a[1]), "r"(a[2]), "r"(a[3]), "r"(b0), "r"(b1));
}

// ============================================================
// Kernel 1: per-row norms, normalized e4m3 copies, pos/diag/l2
// ============================================================
__global__ void __launch_bounds__(256) k_norm(const float* __restrict__ ex) {
    int gw = (blockIdx.x * 256 + threadIdx.x) >> 5;
    int lane = threadIdx.x & 31;
    if (gw >= Nn) return;

    const float4* a4 = reinterpret_cast<const float4*>(ex + (size_t)gw * 2 * Dd);
    const float4* p4 = a4 + Dd / 4;

    float4 av[4], pv[4];
    float an2 = 0.f, pn2 = 0.f, dt = 0.f;
#pragma unroll
    for (int i = 0; i < 4; i++) {
        av[i] = a4[lane + 32 * i];
        pv[i] = p4[lane + 32 * i];
        an2 += av[i].x * av[i].x + av[i].y * av[i].y + av[i].z * av[i].z + av[i].w * av[i].w;
        pn2 += pv[i].x * pv[i].x + pv[i].y * pv[i].y + pv[i].z * pv[i].z + pv[i].w * pv[i].w;
        dt  += av[i].x * pv[i].x + av[i].y * pv[i].y + av[i].z * pv[i].z + av[i].w * pv[i].w;
    }
#pragma unroll
    for (int o = 16; o; o >>= 1) {
        an2 += __shfl_xor_sync(0xffffffffu, an2, o);
        pn2 += __shfl_xor_sync(0xffffffffu, pn2, o);
        dt  += __shfl_xor_sync(0xffffffffu, dt, o);
    }
    float an = sqrtf(an2), pn = sqrtf(pn2);
    float ia = 1.0f / an, ip = 1.0f / pn;

#pragma unroll
    for (int i = 0; i < 4; i++) {
        int byteoff = (lane + 32 * i) * 4;
        uint16_t u01, u23;
        asm("cvt.rn.satfinite.e4m3x2.f32 %0, %1, %2;"
            : "=h"(u01) : "f"(av[i].y * ia), "f"(av[i].x * ia));
        asm("cvt.rn.satfinite.e4m3x2.f32 %0, %1, %2;"
            : "=h"(u23) : "f"(av[i].w * ia), "f"(av[i].z * ia));
        uint32_t w = (uint32_t)u01 | ((uint32_t)u23 << 16);
        *reinterpret_cast<uint32_t*>(&g_A8[(size_t)gw * Dd + byteoff]) = w;

        asm("cvt.rn.satfinite.e4m3x2.f32 %0, %1, %2;"
            : "=h"(u01) : "f"(pv[i].y * ip), "f"(pv[i].x * ip));
        asm("cvt.rn.satfinite.e4m3x2.f32 %0, %1, %2;"
            : "=h"(u23) : "f"(pv[i].w * ip), "f"(pv[i].z * ip));
        w = (uint32_t)u01 | ((uint32_t)u23 << 16);
        *reinterpret_cast<uint32_t*>(&g_P8[(size_t)gw * Dd + byteoff]) = w;
    }
    if (lane == 0) {
        g_pos[gw]   = dt / fmaxf(an * pn, EPSf);
        g_diag[gw]  = an2 / fmaxf(an2, EPSf);
        g_norm2[gw] = an2 + pn2;
    }
}

// ============================================================
// Kernel 2: fp8 mma.sync GEMM, A-resident, 4-stage B pipeline,
// fused exp-row-sum epilogue. grid=(16,64), 256 threads (8 warps 4x2).
// ============================================================
__global__ void __launch_bounds__(256, 1) k_gemm() {
    extern __shared__ __align__(128) unsigned char sm[];
    __shared__ float srow[2][BM];

    const uint32_t smb = (uint32_t)__cvta_generic_to_shared(sm);
    const uint32_t smA = smb;

    const int tid = threadIdx.x;
    const int lane = tid & 31;
    const int warp = tid >> 5;
    const int wm = warp >> 1;     // 0..3
    const int wn = warp & 1;      // 0..1
    const int cc = blockIdx.x;
    const int row0 = blockIdx.y * BM;

    const unsigned char* __restrict__ Ag = g_A8 + (size_t)row0 * Dd;
    const unsigned char* __restrict__ Pg = g_P8 + (size_t)(cc * (JT * BN)) * Dd;

    // ---- prologue: resident A tile (group 0) ----
#pragma unroll
    for (int u = 0; u < 16; u++) {
        int e = tid + u * 256;               // 4096 chunks
        int r = e >> 5, ch = e & 31;
        cpa16(smA + r * 512 + (((uint32_t)(ch ^ (r & 7))) << 4),
              Ag + (size_t)r * Dd + ch * 16);
    }
    cp_commit();

    // ---- prologue: B slabs 0..2 (groups 1..3) ----
#pragma unroll
    for (int p = 0; p < 3; p++) {
        uint32_t dst0 = smb + A_BYTES + (p & 3) * B_STG;
        const unsigned char* Bg = Pg;        // jt=0 for p<8
#pragma unroll
        for (int u = 0; u < 2; u++) {
            int e = tid + u * 256;           // 512 chunks
            int r = e >> 2, ch = e & 3;
            cpa16(dst0 + r * 64 + (((uint32_t)(ch ^ ((r >> 1) & 3))) << 4),
                  Bg + (size_t)r * Dd + p * 64 + ch * 16);
        }
        cp_commit();
    }

    float c[2][8][4];
#pragma unroll
    for (int mi = 0; mi < 2; mi++)
#pragma unroll
        for (int nj = 0; nj < 8; nj++)
#pragma unroll
            for (int k = 0; k < 4; k++) c[mi][nj][k] = 0.f;

    float rowacc[4] = {0.f, 0.f, 0.f, 0.f};

#pragma unroll 1
    for (int sk = 0; sk < JT * KT; sk++) {
        const int kt = sk & 7;
        const int jt = sk >> 3;

        CP_WAIT(2);            // slab sk (and A at sk=0) complete
        __syncthreads();       // all warps done with stage being refilled

        if (sk + 3 < JT * KT) {
            const int psk = sk + 3;
            const int pkt = psk & 7, pjt = psk >> 3;
            uint32_t dst0 = smb + A_BYTES + (psk & 3) * B_STG;
            const unsigned char* Bg = Pg + (size_t)(pjt * BN) * Dd;
#pragma unroll
            for (int u = 0; u < 2; u++) {
                int e = tid + u * 256;
                int r = e >> 2, ch = e & 3;
                cpa16(dst0 + r * 64 + (((uint32_t)(ch ^ ((r >> 1) & 3))) << 4),
                      Bg + (size_t)r * Dd + pkt * 64 + ch * 16);
            }
        }
        cp_commit();

        // ---- compute stage sk&3 against resident A (k = kt*64 .. +63) ----
        const uint32_t bst = smb + A_BYTES + (sk & 3) * B_STG;
#pragma unroll
        for (int ks = 0; ks < 2; ks++) {
            uint32_t a[2][4];
#pragma unroll
            for (int mi = 0; mi < 2; mi++) {
                int r = wm * 32 + mi * 16 + (lane & 7) + ((lane >> 3) & 1) * 8;
                int ch = kt * 4 + ks * 2 + (lane >> 4);
                uint32_t addr = smA + r * 512 + (((uint32_t)(ch ^ (r & 7))) << 4);
                ldm4(a[mi], addr);
            }
#pragma unroll
            for (int ng = 0; ng < 4; ng++) {
                uint32_t b[4];
                int r = wn * 64 + ng * 16 + (lane & 7) + ((lane >> 4) << 3);
                int ch = ks * 2 + ((lane >> 3) & 1);
                uint32_t addr = bst + r * 64 + (((uint32_t)(ch ^ ((r >> 1) & 3))) << 4);
                ldm4(b, addr);
#pragma unroll
                for (int mi = 0; mi < 2; mi++) {
                    mma_fp8(c[mi][2 * ng + 0], a[mi], b[0], b[1]);
                    mma_fp8(c[mi][2 * ng + 1], a[mi], b[2], b[3]);
                }
            }
        }

        // ---- tile finished: fused exp-row-sum epilogue ----
        if (kt == 7) {
            const int jcol = cc * (JT * BN) + jt * BN;
            const bool hd = (row0 == jcol);
#pragma unroll
            for (int mi = 0; mi < 2; mi++) {
                float s0 = 0.f, s1 = 0.f;
                int gi0 = row0 + wm * 32 + mi * 16 + (lane >> 2);
                int gi8 = gi0 + 8;
#pragma unroll
                for (int nj = 0; nj < 8; nj++) {
                    int gj = jcol + wn * 64 + nj * 8 + ((lane & 3) << 1);
                    float v0 = c[mi][nj][0], v1 = c[mi][nj][1];
                    float v2 = c[mi][nj][2], v3 = c[mi][nj][3];
                    if (hd) {
                        if (gi0 == gj)     v0 = g_diag[gi0];
                        if (gi0 == gj + 1) v1 = g_diag[gi0];
                        if (gi8 == gj)     v2 = g_diag[gi8];
                        if (gi8 == gj + 1) v3 = g_diag[gi8];
                    }
                    s0 += __expf(v0) + __expf(v1);
                    s1 += __expf(v2) + __expf(v3);
                    c[mi][nj][0] = 0.f; c[mi][nj][1] = 0.f;
                    c[mi][nj][2] = 0.f; c[mi][nj][3] = 0.f;
                }
                rowacc[mi * 2 + 0] += s0;
                rowacc[mi * 2 + 1] += s1;
            }
        }
    }

    // ---- cross-lane reduce (lanes sharing a row differ in lane&3) ----
#pragma unroll
    for (int k = 0; k < 4; k++) {
        rowacc[k] += __shfl_xor_sync(0xffffffffu, rowacc[k], 1);
        rowacc[k] += __shfl_xor_sync(0xffffffffu, rowacc[k], 2);
    }
    if ((lane & 3) == 0) {
        int lr = wm * 32 + (lane >> 2);
        srow[wn][lr +  0] = rowacc[0];
        srow[wn][lr +  8] = rowacc[1];
        srow[wn][lr + 16] = rowacc[2];
        srow[wn][lr + 24] = rowacc[3];
    }
    __syncthreads();
    if (tid < BM) g_partial[cc][row0 + tid] = srow[0][tid] + srow[1][tid];
}

// ============================================================
// Kernel 3: final deterministic reduction -> scalar loss
// ============================================================
__global__ void __launch_bounds__(1024) k_final(float* __restrict__ out) {
    __shared__ float sL[1024];
    __shared__ float sS[1024];
    int tid = threadIdx.x;
    float loss = 0.f, sq = 0.f;
    for (int i = tid; i < Nn; i += 1024) {
        float rs = 0.f;
#pragma unroll
        for (int cidx = 0; cidx < NCHUNK; cidx++) rs += g_partial[cidx][i];
        float pos = g_pos[i];
        loss += logf(rs + __expf(pos)) - pos;
        sq += g_norm2[i];
    }
    sL[tid] = loss;
    sS[tid] = sq;
    __syncthreads();
    for (int o = 512; o; o >>= 1) {
        if (tid < o) { sL[tid] += sL[tid + o]; sS[tid] += sS[tid + o]; }
        __syncthreads();
    }
    if (tid == 0) out[0] = sL[0] / (float)Nn + 0.02f * sqrtf(sS[0]);
}

// ============================================================
extern "C" void kernel_launch(void* const* d_in, const int* in_sizes, int n_in,
                              void* d_out, int out_size) {
    const float* ex = (const float*)d_in[0];
    (void)in_sizes; (void)n_in; (void)out_size;

    cudaFuncSetAttribute(k_gemm, cudaFuncAttributeMaxDynamicSharedMemorySize, DYN_SMEM);

    k_norm<<<Nn / 8, 256>>>(ex);

    dim3 g(NCHUNK, Nn / BM);
    k_gemm<<<g, 256, DYN_SMEM>>>();

    k_final<<<1, 1024>>>((float*)d_out);
}

// round 4
// speedup vs baseline: 1.7663x; 1.1514x over previous
#include <cuda_runtime.h>
#include <cuda_bf16.h>
#include <cstdint>

#define Nn 8192
#define Dd 512
#define EPSf 1e-8f

#define NCHUNK 16        // col chunks (grid.x)
#define JT 4             // 128-col tiles per chunk
#define KT 8             // K steps of 64 bytes
#define NST 4            // B pipeline stages
#define BM 128
#define BN 128

#define A_BYTES (BM * Dd)       // 65536 — A tile resident
#define B_STG (BN * 64)         // 8192 per stage
#define DYN_SMEM (A_BYTES + NST * B_STG)   // 98304

// ---- scratch ----
__device__ unsigned char g_A8[(size_t)Nn * Dd];
__device__ unsigned char g_P8[(size_t)Nn * Dd];
__device__ float g_pos[Nn];
__device__ float g_diag[Nn];
__device__ float g_norm2[Nn];
__device__ float g_partial[NCHUNK][Nn];

__device__ __forceinline__ void cpa16(uint32_t dst, const void* src) {
    asm volatile("cp.async.cg.shared.global [%0], [%1], 16;\n" :: "r"(dst), "l"(src));
}
__device__ __forceinline__ void cp_commit() {
    asm volatile("cp.async.commit_group;\n" ::);
}
#define CP_WAIT(n) asm volatile("cp.async.wait_group %0;\n" :: "n"(n))

__device__ __forceinline__ void ldm4(uint32_t* r, uint32_t addr) {
    asm volatile("ldmatrix.sync.aligned.m8n8.x4.shared.b16 {%0,%1,%2,%3}, [%4];\n"
                 : "=r"(r[0]), "=r"(r[1]), "=r"(r[2]), "=r"(r[3]) : "r"(addr));
}
__device__ __forceinline__ void mma_fp8(float* c, const uint32_t* a, uint32_t b0, uint32_t b1) {
    asm volatile(
        "mma.sync.aligned.m16n8k32.row.col.f32.e4m3.e4m3.f32 "
        "{%0,%1,%2,%3}, {%4,%5,%6,%7}, {%8,%9}, {%0,%1,%2,%3};\n"
        : "+f"(c[0]), "+f"(c[1]), "+f"(c[2]), "+f"(c[3])
        : "r"(a[0]), "r"(a[1]), "r"(a[2]), "r"(a[3]), "r"(b0), "r"(b1));
}

// ============================================================
// Kernel 1: per-row norms, normalized e4m3 copies, pos/diag/l2
// ============================================================
__global__ void __launch_bounds__(256) k_norm(const float* __restrict__ ex) {
    int gw = (blockIdx.x * 256 + threadIdx.x) >> 5;
    int lane = threadIdx.x & 31;
    if (gw >= Nn) return;

    const float4* a4 = reinterpret_cast<const float4*>(ex + (size_t)gw * 2 * Dd);
    const float4* p4 = a4 + Dd / 4;

    float4 av[4], pv[4];
    float an2 = 0.f, pn2 = 0.f, dt = 0.f;
#pragma unroll
    for (int i = 0; i < 4; i++) {
        av[i] = a4[lane + 32 * i];
        pv[i] = p4[lane + 32 * i];
        an2 += av[i].x * av[i].x + av[i].y * av[i].y + av[i].z * av[i].z + av[i].w * av[i].w;
        pn2 += pv[i].x * pv[i].x + pv[i].y * pv[i].y + pv[i].z * pv[i].z + pv[i].w * pv[i].w;
        dt  += av[i].x * pv[i].x + av[i].y * pv[i].y + av[i].z * pv[i].z + av[i].w * pv[i].w;
    }
#pragma unroll
    for (int o = 16; o; o >>= 1) {
        an2 += __shfl_xor_sync(0xffffffffu, an2, o);
        pn2 += __shfl_xor_sync(0xffffffffu, pn2, o);
        dt  += __shfl_xor_sync(0xffffffffu, dt, o);
    }
    float an = sqrtf(an2), pn = sqrtf(pn2);
    float ia = 1.0f / an, ip = 1.0f / pn;

#pragma unroll
    for (int i = 0; i < 4; i++) {
        int byteoff = (lane + 32 * i) * 4;
        uint16_t u01, u23;
        asm("cvt.rn.satfinite.e4m3x2.f32 %0, %1, %2;"
            : "=h"(u01) : "f"(av[i].y * ia), "f"(av[i].x * ia));
        asm("cvt.rn.satfinite.e4m3x2.f32 %0, %1, %2;"
            : "=h"(u23) : "f"(av[i].w * ia), "f"(av[i].z * ia));
        uint32_t w = (uint32_t)u01 | ((uint32_t)u23 << 16);
        *reinterpret_cast<uint32_t*>(&g_A8[(size_t)gw * Dd + byteoff]) = w;

        asm("cvt.rn.satfinite.e4m3x2.f32 %0, %1, %2;"
            : "=h"(u01) : "f"(pv[i].y * ip), "f"(pv[i].x * ip));
        asm("cvt.rn.satfinite.e4m3x2.f32 %0, %1, %2;"
            : "=h"(u23) : "f"(pv[i].w * ip), "f"(pv[i].z * ip));
        w = (uint32_t)u01 | ((uint32_t)u23 << 16);
        *reinterpret_cast<uint32_t*>(&g_P8[(size_t)gw * Dd + byteoff]) = w;
    }
    if (lane == 0) {
        g_pos[gw]   = dt / fmaxf(an * pn, EPSf);
        g_diag[gw]  = an2 / fmaxf(an2, EPSf);
        g_norm2[gw] = an2 + pn2;
    }
}

// ============================================================
// Kernel 2: fp8 mma.sync GEMM, A-resident, 4-stage B pipeline,
// fused exp-row-sum epilogue. grid=(16,64), 256 threads (8 warps 4x2),
// 2 CTAs/SM for latency hiding.
// ============================================================
__global__ void __launch_bounds__(256, 2) k_gemm() {
    extern __shared__ __align__(128) unsigned char sm[];
    __shared__ float srow[2][BM];

    const uint32_t smb = (uint32_t)__cvta_generic_to_shared(sm);
    const uint32_t smA = smb;

    const int tid = threadIdx.x;
    const int lane = tid & 31;
    const int warp = tid >> 5;
    const int wm = warp >> 1;     // 0..3
    const int wn = warp & 1;      // 0..1
    const int cc = blockIdx.x;
    const int row0 = blockIdx.y * BM;

    const unsigned char* __restrict__ Ag = g_A8 + (size_t)row0 * Dd;
    const unsigned char* __restrict__ Pg = g_P8 + (size_t)(cc * (JT * BN)) * Dd;

    // ---- prologue: resident A tile (group 0) ----
#pragma unroll
    for (int u = 0; u < 16; u++) {
        int e = tid + u * 256;               // 4096 chunks
        int r = e >> 5, ch = e & 31;
        cpa16(smA + r * 512 + (((uint32_t)(ch ^ (r & 7))) << 4),
              Ag + (size_t)r * Dd + ch * 16);
    }
    cp_commit();

    // ---- prologue: B slabs 0..2 (groups 1..3) ----
#pragma unroll
    for (int p = 0; p < 3; p++) {
        uint32_t dst0 = smb + A_BYTES + (p & 3) * B_STG;
        const unsigned char* Bg = Pg;        // jt=0 for p<8
#pragma unroll
        for (int u = 0; u < 2; u++) {
            int e = tid + u * 256;           // 512 chunks
            int r = e >> 2, ch = e & 3;
            cpa16(dst0 + r * 64 + (((uint32_t)(ch ^ ((r >> 1) & 3))) << 4),
                  Bg + (size_t)r * Dd + p * 64 + ch * 16);
        }
        cp_commit();
    }

    float c[2][8][4];
#pragma unroll
    for (int mi = 0; mi < 2; mi++)
#pragma unroll
        for (int nj = 0; nj < 8; nj++)
#pragma unroll
            for (int k = 0; k < 4; k++) c[mi][nj][k] = 0.f;

    float rowacc[4] = {0.f, 0.f, 0.f, 0.f};

    // hoisted invariant swizzled offsets
    uint32_t a_off[2], b_off[4];
#pragma unroll
    for (int mi = 0; mi < 2; mi++) {
        int r = wm * 32 + mi * 16 + (lane & 7) + ((lane >> 3) & 1) * 8;
        a_off[mi] = smA + r * 512 + ((uint32_t)(r & 7) << 4);   // ^ ch applied later
    }
#pragma unroll
    for (int ng = 0; ng < 4; ng++) {
        int r = wn * 64 + ng * 16 + (lane & 7) + ((lane >> 4) << 3);
        b_off[ng] = r * 64 + ((uint32_t)((r >> 1) & 3) << 4);
    }
    const int a_chb = (lane >> 4);            // 0/1
    const int b_chb = ((lane >> 3) & 1);      // 0/1

#pragma unroll 1
    for (int sk = 0; sk < JT * KT; sk++) {
        const int kt = sk & 7;
        const int jt = sk >> 3;

        CP_WAIT(2);            // slab sk (and A at sk=0) complete
        __syncthreads();       // all warps done with stage being refilled

        if (sk + 3 < JT * KT) {
            const int psk = sk + 3;
            const int pkt = psk & 7, pjt = psk >> 3;
            uint32_t dst0 = smb + A_BYTES + (psk & 3) * B_STG;
            const unsigned char* Bg = Pg + (size_t)(pjt * BN) * Dd;
#pragma unroll
            for (int u = 0; u < 2; u++) {
                int e = tid + u * 256;
                int r = e >> 2, ch = e & 3;
                cpa16(dst0 + r * 64 + (((uint32_t)(ch ^ ((r >> 1) & 3))) << 4),
                      Bg + (size_t)r * Dd + pkt * 64 + ch * 16);
            }
        }
        cp_commit();

        // ---- compute stage sk&3 against resident A (k = kt*64 .. +63) ----
        const uint32_t bst = smb + A_BYTES + (sk & 3) * B_STG;
#pragma unroll
        for (int ks = 0; ks < 2; ks++) {
            uint32_t a[2][4];
            const uint32_t a_chx = (uint32_t)((kt * 4 + ks * 2 + a_chb)) << 4;
#pragma unroll
            for (int mi = 0; mi < 2; mi++)
                ldm4(a[mi], a_off[mi] ^ a_chx);
            const uint32_t b_chx = (uint32_t)(ks * 2 + b_chb) << 4;
#pragma unroll
            for (int ng = 0; ng < 4; ng++) {
                uint32_t b[4];
                ldm4(b, bst + (b_off[ng] ^ b_chx));
#pragma unroll
                for (int mi = 0; mi < 2; mi++) {
                    mma_fp8(c[mi][2 * ng + 0], a[mi], b[0], b[1]);
                    mma_fp8(c[mi][2 * ng + 1], a[mi], b[2], b[3]);
                }
            }
        }

        // ---- tile finished: fused exp-row-sum epilogue ----
        if (kt == 7) {
            const int jcol = cc * (JT * BN) + jt * BN;
            const bool hd = (row0 == jcol);
#pragma unroll
            for (int mi = 0; mi < 2; mi++) {
                float s0 = 0.f, s1 = 0.f;
                int gi0 = row0 + wm * 32 + mi * 16 + (lane >> 2);
                int gi8 = gi0 + 8;
#pragma unroll
                for (int nj = 0; nj < 8; nj++) {
                    int gj = jcol + wn * 64 + nj * 8 + ((lane & 3) << 1);
                    float v0 = c[mi][nj][0], v1 = c[mi][nj][1];
                    float v2 = c[mi][nj][2], v3 = c[mi][nj][3];
                    if (hd) {
                        if (gi0 == gj)     v0 = g_diag[gi0];
                        if (gi0 == gj + 1) v1 = g_diag[gi0];
                        if (gi8 == gj)     v2 = g_diag[gi8];
                        if (gi8 == gj + 1) v3 = g_diag[gi8];
                    }
                    s0 += __expf(v0) + __expf(v1);
                    s1 += __expf(v2) + __expf(v3);
                    c[mi][nj][0] = 0.f; c[mi][nj][1] = 0.f;
                    c[mi][nj][2] = 0.f; c[mi][nj][3] = 0.f;
                }
                rowacc[mi * 2 + 0] += s0;
                rowacc[mi * 2 + 1] += s1;
            }
        }
    }

    // ---- cross-lane reduce (lanes sharing a row differ in lane&3) ----
#pragma unroll
    for (int k = 0; k < 4; k++) {
        rowacc[k] += __shfl_xor_sync(0xffffffffu, rowacc[k], 1);
        rowacc[k] += __shfl_xor_sync(0xffffffffu, rowacc[k], 2);
    }
    if ((lane & 3) == 0) {
        int lr = wm * 32 + (lane >> 2);
        srow[wn][lr +  0] = rowacc[0];
        srow[wn][lr +  8] = rowacc[1];
        srow[wn][lr + 16] = rowacc[2];
        srow[wn][lr + 24] = rowacc[3];
    }
    __syncthreads();
    if (tid < BM) g_partial[cc][row0 + tid] = srow[0][tid] + srow[1][tid];
}

// ============================================================
// Kernel 3: final deterministic reduction -> scalar loss
// ============================================================
__global__ void __launch_bounds__(1024) k_final(float* __restrict__ out) {
    __shared__ float sL[1024];
    __shared__ float sS[1024];
    int tid = threadIdx.x;
    float loss = 0.f, sq = 0.f;
    for (int i = tid; i < Nn; i += 1024) {
        float rs = 0.f;
#pragma unroll
        for (int cidx = 0; cidx < NCHUNK; cidx++) rs += g_partial[cidx][i];
        float pos = g_pos[i];
        loss += logf(rs + __expf(pos)) - pos;
        sq += g_norm2[i];
    }
    sL[tid] = loss;
    sS[tid] = sq;
    __syncthreads();
    for (int o = 512; o; o >>= 1) {
        if (tid < o) { sL[tid] += sL[tid + o]; sS[tid] += sS[tid + o]; }
        __syncthreads();
    }
    if (tid == 0) out[0] = sL[0] / (float)Nn + 0.02f * sqrtf(sS[0]);
}

// ============================================================
extern "C" void kernel_launch(void* const* d_in, const int* in_sizes, int n_in,
                              void* d_out, int out_size) {
    const float* ex = (const float*)d_in[0];
    (void)in_sizes; (void)n_in; (void)out_size;

    cudaFuncSetAttribute(k_gemm, cudaFuncAttributeMaxDynamicSharedMemorySize, DYN_SMEM);

    k_norm<<<Nn / 8, 256>>>(ex);

    dim3 g(NCHUNK, Nn / BM);
    k_gemm<<<g, 256, DYN_SMEM>>>();

    k_final<<<1, 1024>>>((float*)d_out);
}